// round 4
// baseline (speedup 1.0000x reference)
#include <cuda_runtime.h>

// ---------------- problem constants ------------------------------------------
#define MAX_N 100000
#define MAX_E 1600000

// ---------------- device scratch (allocation-free rule) ----------------------
__device__ float g_dis[MAX_N];          // deg -> deg^{-1/2}
__device__ int   g_src[MAX_E];
__device__ int   g_dst[MAX_E];
__device__ float g_norm[MAX_E];
__device__ __align__(16) float g_bufA[MAX_N * 96];
__device__ __align__(16) float g_bufB[MAX_N * 96];
__device__ __align__(16) float g_bufH[MAX_N * 96];

// ---------------- setup kernels ----------------------------------------------
__global__ void k_init_deg(int n) {
    int i = blockIdx.x * blockDim.x + threadIdx.x;
    if (i < n) g_dis[i] = 1.0f;   // self-loop contributes 1 to degree
}

// edge_index is INT32 (JAX x64 disabled: randint(dtype=int64) materializes int32).
__global__ void k_count_deg(const int* __restrict__ ei, int e, int n) {
    int i = blockIdx.x * blockDim.x + threadIdx.x;
    if (i >= e) return;
    int s = ei[i];
    int d = ei[e + i];
    // defensive clamp: a bad index must surface as rel_err, never as a trap
    if ((unsigned)s >= (unsigned)n) s = 0;
    if ((unsigned)d >= (unsigned)n) d = 0;
    g_src[i] = s;
    g_dst[i] = d;
    atomicAdd(&g_dis[d], 1.0f);
}

__global__ void k_rsqrt(int n) {
    int i = blockIdx.x * blockDim.x + threadIdx.x;
    if (i < n) g_dis[i] = rsqrtf(g_dis[i]);
}

__global__ void k_norm(int e) {
    int i = blockIdx.x * blockDim.x + threadIdx.x;
    if (i >= e) return;
    g_norm[i] = g_dis[g_src[i]] * g_dis[g_dst[i]];
}

// ---------------- agg init: agg[v] = h[v]*dis[v]^2 ----------------------------
template <int F>
__global__ void k_init_agg(const float* __restrict__ h, float* __restrict__ agg, int n) {
    constexpr int NV = F / 4;
    int tid = blockIdx.x * blockDim.x + threadIdx.x;
    if (tid >= n * NV) return;
    int node = tid / NV;
    int v = tid - node * NV;
    float dis = g_dis[node];
    float d2 = dis * dis;
    float4 hv = *reinterpret_cast<const float4*>(h + (size_t)node * F + v * 4);
    float4 o;
    o.x = hv.x * d2; o.y = hv.y * d2; o.z = hv.z * d2; o.w = hv.w * d2;
    *reinterpret_cast<float4*>(agg + (size_t)node * F + v * 4) = o;
}

// ---------------- edge scatter: agg[dst] += h[src]*norm -----------------------
template <int F>
__global__ void k_scatter(const float* __restrict__ h, float* __restrict__ agg, int e) {
    constexpr int NV = F / 4;                 // 16 / 8 / 4 (power of two)
    int tid = blockIdx.x * blockDim.x + threadIdx.x;
    if (tid >= e * NV) return;
    int ed = tid / NV;
    int v = tid - ed * NV;
    int s = g_src[ed];
    int d = g_dst[ed];
    float w = g_norm[ed];
    float4 hv = *reinterpret_cast<const float4*>(h + (size_t)s * F + (v << 2));
    float* p = agg + (size_t)d * F + (v << 2);
    atomicAdd(p + 0, hv.x * w);
    atomicAdd(p + 1, hv.y * w);
    atomicAdd(p + 2, hv.z * w);
    atomicAdd(p + 3, hv.w * w);
}

// ---------------- fused GEMM: out = act(in) @ W (+bh); optional agg init ------
// Block: 128 threads = 128 nodes. Xs staged transposed [FIN][129] (conflict-free),
// W fully staged. 16 fp32 accumulators per thread, float4 broadcast W loads.
template <int FIN, int FOUT, bool RELU, bool BIASH, bool DOAGG>
__global__ void __launch_bounds__(128)
k_gemm(const float* __restrict__ in, const float* __restrict__ W,
       const float* __restrict__ bh, float* __restrict__ out,
       float* __restrict__ agg, const float* __restrict__ bagg, int n) {
    extern __shared__ float sm[];
    float* Xs = sm;                 // [FIN][129]
    float* Ws = sm + FIN * 129;     // [FIN][FOUT]
    const int tid = threadIdx.x;
    const int base = blockIdx.x * 128;

    for (int i = tid; i < FIN * FOUT; i += 128) Ws[i] = W[i];

    const int rows = (n - base < 128) ? (n - base) : 128;
    for (int i = tid; i < FIN * 128; i += 128) {
        int nl = i / FIN;
        int k = i - nl * FIN;
        float v = 0.0f;
        if (nl < rows) {
            v = in[(size_t)(base + nl) * FIN + k];
            if (RELU) v = fmaxf(v, 0.0f);
        }
        Xs[k * 129 + nl] = v;
    }
    __syncthreads();

    const int node = base + tid;
    const bool valid = node < n;
    float d2 = 0.0f;
    if (DOAGG && valid) {
        float dis = g_dis[node];
        d2 = dis * dis;
    }

    for (int c0 = 0; c0 < FOUT; c0 += 16) {
        float acc[16];
#pragma unroll
        for (int j = 0; j < 16; j++) acc[j] = BIASH ? __ldg(&bh[c0 + j]) : 0.0f;

#pragma unroll 4
        for (int k = 0; k < FIN; k++) {
            float xv = Xs[k * 129 + tid];
            const float4* wr = reinterpret_cast<const float4*>(Ws + k * FOUT + c0);
#pragma unroll
            for (int j = 0; j < 4; j++) {
                float4 w = wr[j];
                acc[4 * j + 0] += xv * w.x;
                acc[4 * j + 1] += xv * w.y;
                acc[4 * j + 2] += xv * w.z;
                acc[4 * j + 3] += xv * w.w;
            }
        }

        if (valid) {
            float4* op = reinterpret_cast<float4*>(out + (size_t)node * FOUT + c0);
#pragma unroll
            for (int j = 0; j < 4; j++) {
                float4 o = {acc[4 * j], acc[4 * j + 1], acc[4 * j + 2], acc[4 * j + 3]};
                op[j] = o;
            }
            if (DOAGG) {
                float4* ap = reinterpret_cast<float4*>(agg + (size_t)node * FOUT + c0);
#pragma unroll
                for (int j = 0; j < 4; j++) {
                    float4 o = {acc[4 * j + 0] * d2 + bagg[c0 + 4 * j + 0],
                                acc[4 * j + 1] * d2 + bagg[c0 + 4 * j + 1],
                                acc[4 * j + 2] * d2 + bagg[c0 + 4 * j + 2],
                                acc[4 * j + 3] * d2 + bagg[c0 + 4 * j + 3]};
                    ap[j] = o;
                }
            }
        }
    }
}

// ---------------- launch -------------------------------------------------------
extern "C" void kernel_launch(void* const* d_in, const int* in_sizes, int n_in,
                              void* d_out, int out_size) {
    const float* x  = (const float*)d_in[0];
    const int*   ei = (const int*)d_in[1];   // int32! (JAX x64 disabled)
    const float* W1 = (const float*)d_in[2]; const float* b1 = (const float*)d_in[3];
    const float* W2 = (const float*)d_in[4]; const float* b2 = (const float*)d_in[5];
    const float* W3 = (const float*)d_in[6]; const float* b3 = (const float*)d_in[7];
    const float* W4 = (const float*)d_in[8]; const float* b4 = (const float*)d_in[9];
    float* out = (float*)d_out;

    const int n = in_sizes[0] / 64;
    const int e = in_sizes[1] / 2;

    float *bufA, *bufB, *bufH;
    cudaGetSymbolAddress((void**)&bufA, g_bufA);
    cudaGetSymbolAddress((void**)&bufB, g_bufB);
    cudaGetSymbolAddress((void**)&bufH, g_bufH);

    // dynamic smem sizes per GEMM instantiation
    const int s1 = (64 * 129 + 64 * 96) * 4;  // 57600
    const int s2 = (96 * 129 + 96 * 64) * 4;  // 74112
    const int s3 = (64 * 129 + 64 * 32) * 4;  // 41216
    const int s4 = (32 * 129 + 32 * 16) * 4;  // 18560
    cudaFuncSetAttribute(k_gemm<64, 96, false, true,  false>, cudaFuncAttributeMaxDynamicSharedMemorySize, s1);
    cudaFuncSetAttribute(k_gemm<96, 64, true,  false, true>,  cudaFuncAttributeMaxDynamicSharedMemorySize, s2);
    cudaFuncSetAttribute(k_gemm<64, 32, true,  false, true>,  cudaFuncAttributeMaxDynamicSharedMemorySize, s3);
    cudaFuncSetAttribute(k_gemm<32, 16, true,  false, true>,  cudaFuncAttributeMaxDynamicSharedMemorySize, s4);

    const int TB = 256;
    const int nb_n = (n + TB - 1) / TB;
    const int nb_e = (e + TB - 1) / TB;
    const int gblk = (n + 127) / 128;

    // ---- degree / norm setup (runs every replay; deterministic) ----
    k_init_deg<<<nb_n, TB>>>(n);
    k_count_deg<<<nb_e, TB>>>(ei, e, n);
    k_rsqrt<<<nb_n, TB>>>(n);
    k_norm<<<nb_e, TB>>>(e);

    // ---- layer 1: aggregate-first at width 64 (A x) then GEMM 64->96 ----
    k_init_agg<64><<<(n * 16 + TB - 1) / TB, TB>>>(x, bufA, n);
    k_scatter<64><<<(e * 16 + TB - 1) / TB, TB>>>(x, bufA, e);
    k_gemm<64, 96, false, true, false><<<gblk, 128, s1>>>(bufA, W1, b1, bufB, nullptr, nullptr, n);

    // ---- layer 2: h2 = relu(h1)@W2 (96->64), fused agg init, scatter@64 ----
    k_gemm<96, 64, true, false, true><<<gblk, 128, s2>>>(bufB, W2, nullptr, bufH, bufA, b2, n);
    k_scatter<64><<<(e * 16 + TB - 1) / TB, TB>>>(bufH, bufA, e);

    // ---- layer 3: h3 = relu(agg2)@W3 (64->32), fused agg init, scatter@32 ----
    k_gemm<64, 32, true, false, true><<<gblk, 128, s3>>>(bufA, W3, nullptr, bufH, bufB, b3, n);
    k_scatter<32><<<(e * 8 + TB - 1) / TB, TB>>>(bufH, bufB, e);

    // ---- layer 4: h4 = relu(agg3)@W4 (32->16), agg init straight into d_out ----
    k_gemm<32, 16, true, false, true><<<gblk, 128, s4>>>(bufB, W4, nullptr, bufH, out, b4, n);
    k_scatter<16><<<(e * 4 + TB - 1) / TB, TB>>>(bufH, out, e);
}

// round 5
// speedup vs baseline: 1.6456x; 1.6456x over previous
#include <cuda_runtime.h>

// ---------------- problem constants ------------------------------------------
#define MAX_N 100000
#define MAX_E 1600000

// ---------------- device scratch (allocation-free rule) ----------------------
__device__ float g_dis[MAX_N];          // deg -> deg^{-1/2}
__device__ int   g_src[MAX_E];
__device__ int   g_dst[MAX_E];
__device__ float g_norm[MAX_E];
__device__ __align__(16) float g_bufA[MAX_N * 96];
__device__ __align__(16) float g_bufB[MAX_N * 96];
__device__ __align__(16) float g_bufH[MAX_N * 96];

// ---------------- setup kernels ----------------------------------------------
__global__ void k_init_deg(int n) {
    int i = blockIdx.x * blockDim.x + threadIdx.x;
    if (i < n) g_dis[i] = 1.0f;   // self-loop contributes 1 to degree
}

// edge_index is INT32 (JAX x64 disabled: randint(dtype=int64) materializes int32).
__global__ void k_count_deg(const int* __restrict__ ei, int e, int n) {
    int i = blockIdx.x * blockDim.x + threadIdx.x;
    if (i >= e) return;
    int s = ei[i];
    int d = ei[e + i];
    if ((unsigned)s >= (unsigned)n) s = 0;   // bad index -> rel_err, never a trap
    if ((unsigned)d >= (unsigned)n) d = 0;
    g_src[i] = s;
    g_dst[i] = d;
    atomicAdd(&g_dis[d], 1.0f);
}

__global__ void k_rsqrt(int n) {
    int i = blockIdx.x * blockDim.x + threadIdx.x;
    if (i < n) g_dis[i] = rsqrtf(g_dis[i]);
}

__global__ void k_norm(int e) {
    int i = blockIdx.x * blockDim.x + threadIdx.x;
    if (i >= e) return;
    g_norm[i] = g_dis[g_src[i]] * g_dis[g_dst[i]];
}

// ---------------- agg init: agg[v] = h[v]*dis[v]^2 ----------------------------
template <int F>
__global__ void k_init_agg(const float* __restrict__ h, float* __restrict__ agg, int n) {
    constexpr int NV = F / 4;
    int tid = blockIdx.x * blockDim.x + threadIdx.x;
    if (tid >= n * NV) return;
    int node = tid / NV;
    int v = tid - node * NV;
    float dis = g_dis[node];
    float d2 = dis * dis;
    float4 hv = *reinterpret_cast<const float4*>(h + (size_t)node * F + v * 4);
    float4 o;
    o.x = hv.x * d2; o.y = hv.y * d2; o.z = hv.z * d2; o.w = hv.w * d2;
    *reinterpret_cast<float4*>(agg + (size_t)node * F + v * 4) = o;
}

// ---------------- edge scatter: agg[dst] += h[src]*norm -----------------------
// R4 proved the R1-R3 traps were bad addresses (int64 misread), not the RED
// instruction: scalar atomics trapped identically. Vector RED retried here.
template <int F>
__global__ void k_scatter(const float* __restrict__ h, float* __restrict__ agg, int e) {
    constexpr int NV = F / 4;                 // 16 / 8 / 4 (power of two)
    int tid = blockIdx.x * blockDim.x + threadIdx.x;
    if (tid >= e * NV) return;
    int ed = tid / NV;
    int v = tid - ed * NV;
    int s = g_src[ed];
    int d = g_dst[ed];
    float w = g_norm[ed];
    float4 hv = *reinterpret_cast<const float4*>(h + (size_t)s * F + (v << 2));
    float4 m;
    m.x = hv.x * w; m.y = hv.y * w; m.z = hv.z * w; m.w = hv.w * w;
#if defined(__CUDA_ARCH__) && (__CUDA_ARCH__ >= 900)
    atomicAdd(reinterpret_cast<float4*>(agg + (size_t)d * F + (v << 2)), m);
#else
    float* p = agg + (size_t)d * F + (v << 2);
    atomicAdd(p + 0, m.x);
    atomicAdd(p + 1, m.y);
    atomicAdd(p + 2, m.z);
    atomicAdd(p + 3, m.w);
#endif
}

// ---------------- fused GEMM: out = act(in) @ W (+bh); optional agg init ------
template <int FIN, int FOUT, bool RELU, bool BIASH, bool DOAGG>
__global__ void __launch_bounds__(128)
k_gemm(const float* __restrict__ in, const float* __restrict__ W,
       const float* __restrict__ bh, float* __restrict__ out,
       float* __restrict__ agg, const float* __restrict__ bagg, int n) {
    extern __shared__ float sm[];
    float* Xs = sm;                 // [FIN][129]
    float* Ws = sm + FIN * 129;     // [FIN][FOUT]
    const int tid = threadIdx.x;
    const int base = blockIdx.x * 128;

    for (int i = tid; i < FIN * FOUT; i += 128) Ws[i] = W[i];

    const int rows = (n - base < 128) ? (n - base) : 128;
    for (int i = tid; i < FIN * 128; i += 128) {
        int nl = i / FIN;
        int k = i - nl * FIN;
        float v = 0.0f;
        if (nl < rows) {
            v = in[(size_t)(base + nl) * FIN + k];
            if (RELU) v = fmaxf(v, 0.0f);
        }
        Xs[k * 129 + nl] = v;
    }
    __syncthreads();

    const int node = base + tid;
    const bool valid = node < n;
    float d2 = 0.0f;
    if (DOAGG && valid) {
        float dis = g_dis[node];
        d2 = dis * dis;
    }

    for (int c0 = 0; c0 < FOUT; c0 += 16) {
        float acc[16];
#pragma unroll
        for (int j = 0; j < 16; j++) acc[j] = BIASH ? __ldg(&bh[c0 + j]) : 0.0f;

#pragma unroll 4
        for (int k = 0; k < FIN; k++) {
            float xv = Xs[k * 129 + tid];
            const float4* wr = reinterpret_cast<const float4*>(Ws + k * FOUT + c0);
#pragma unroll
            for (int j = 0; j < 4; j++) {
                float4 w = wr[j];
                acc[4 * j + 0] += xv * w.x;
                acc[4 * j + 1] += xv * w.y;
                acc[4 * j + 2] += xv * w.z;
                acc[4 * j + 3] += xv * w.w;
            }
        }

        if (valid) {
            float4* op = reinterpret_cast<float4*>(out + (size_t)node * FOUT + c0);
#pragma unroll
            for (int j = 0; j < 4; j++) {
                float4 o = {acc[4 * j], acc[4 * j + 1], acc[4 * j + 2], acc[4 * j + 3]};
                op[j] = o;
            }
            if (DOAGG) {
                float4* ap = reinterpret_cast<float4*>(agg + (size_t)node * FOUT + c0);
#pragma unroll
                for (int j = 0; j < 4; j++) {
                    float4 o = {acc[4 * j + 0] * d2 + bagg[c0 + 4 * j + 0],
                                acc[4 * j + 1] * d2 + bagg[c0 + 4 * j + 1],
                                acc[4 * j + 2] * d2 + bagg[c0 + 4 * j + 2],
                                acc[4 * j + 3] * d2 + bagg[c0 + 4 * j + 3]};
                    ap[j] = o;
                }
            }
        }
    }
}

// ---------------- launch -------------------------------------------------------
extern "C" void kernel_launch(void* const* d_in, const int* in_sizes, int n_in,
                              void* d_out, int out_size) {
    const float* x  = (const float*)d_in[0];
    const int*   ei = (const int*)d_in[1];   // int32! (JAX x64 disabled)
    const float* W1 = (const float*)d_in[2]; const float* b1 = (const float*)d_in[3];
    const float* W2 = (const float*)d_in[4]; const float* b2 = (const float*)d_in[5];
    const float* W3 = (const float*)d_in[6]; const float* b3 = (const float*)d_in[7];
    const float* W4 = (const float*)d_in[8]; const float* b4 = (const float*)d_in[9];
    float* out = (float*)d_out;

    const int n = in_sizes[0] / 64;
    const int e = in_sizes[1] / 2;

    float *bufA, *bufB, *bufH;
    cudaGetSymbolAddress((void**)&bufA, g_bufA);
    cudaGetSymbolAddress((void**)&bufB, g_bufB);
    cudaGetSymbolAddress((void**)&bufH, g_bufH);

    const int s1 = (64 * 129 + 64 * 96) * 4;  // 57600
    const int s2 = (96 * 129 + 96 * 64) * 4;  // 74112
    const int s3 = (64 * 129 + 64 * 32) * 4;  // 41216
    const int s4 = (32 * 129 + 32 * 16) * 4;  // 18560
    cudaFuncSetAttribute(k_gemm<64, 96, false, true,  false>, cudaFuncAttributeMaxDynamicSharedMemorySize, s1);
    cudaFuncSetAttribute(k_gemm<96, 64, true,  false, true>,  cudaFuncAttributeMaxDynamicSharedMemorySize, s2);
    cudaFuncSetAttribute(k_gemm<64, 32, true,  false, true>,  cudaFuncAttributeMaxDynamicSharedMemorySize, s3);
    cudaFuncSetAttribute(k_gemm<32, 16, true,  false, true>,  cudaFuncAttributeMaxDynamicSharedMemorySize, s4);

    const int TB = 256;
    const int nb_n = (n + TB - 1) / TB;
    const int nb_e = (e + TB - 1) / TB;
    const int gblk = (n + 127) / 128;

    // ---- degree / norm setup ----
    k_init_deg<<<nb_n, TB>>>(n);
    k_count_deg<<<nb_e, TB>>>(ei, e, n);
    k_rsqrt<<<nb_n, TB>>>(n);
    k_norm<<<nb_e, TB>>>(e);

    // ---- layer 1: aggregate-first at width 64 (A x) then GEMM 64->96 ----
    k_init_agg<64><<<(n * 16 + TB - 1) / TB, TB>>>(x, bufA, n);
    k_scatter<64><<<(e * 16 + TB - 1) / TB, TB>>>(x, bufA, e);
    k_gemm<64, 96, false, true, false><<<gblk, 128, s1>>>(bufA, W1, b1, bufB, nullptr, nullptr, n);

    // ---- layer 2: h2 = relu(h1)@W2 (96->64), fused agg init, scatter@64 ----
    k_gemm<96, 64, true, false, true><<<gblk, 128, s2>>>(bufB, W2, nullptr, bufH, bufA, b2, n);
    k_scatter<64><<<(e * 16 + TB - 1) / TB, TB>>>(bufH, bufA, e);

    // ---- layer 3: h3 = relu(agg2)@W3 (64->32), fused agg init, scatter@32 ----
    k_gemm<64, 32, true, false, true><<<gblk, 128, s3>>>(bufA, W3, nullptr, bufH, bufB, b3, n);
    k_scatter<32><<<(e * 8 + TB - 1) / TB, TB>>>(bufH, bufB, e);

    // ---- layer 4: h4 = relu(agg3)@W4 (32->16), agg init straight into d_out ----
    k_gemm<32, 16, true, false, true><<<gblk, 128, s4>>>(bufB, W4, nullptr, bufH, out, b4, n);
    k_scatter<16><<<(e * 4 + TB - 1) / TB, TB>>>(bufH, out, e);
}

// round 6
// speedup vs baseline: 2.2354x; 1.3584x over previous
#include <cuda_runtime.h>

// ---------------- problem constants ------------------------------------------
#define MAX_N 100000
#define MAX_E 1600000
#define SCAN_B 512

// ---------------- device scratch (allocation-free rule) ----------------------
__device__ int   g_deg[MAX_N];          // in-degree (dst), excl. self loop
__device__ float g_dis[MAX_N];          // (deg+1)^{-1/2}
__device__ int   g_row[MAX_N];          // CSR row start
__device__ int   g_cur[MAX_N];          // bucket cursor
__device__ int   g_bsum[SCAN_B];        // scan partials
__device__ int   g_boff[SCAN_B];
__device__ int   g_src[MAX_E];
__device__ int   g_dst[MAX_E];
__device__ int   g_esrc[MAX_E];         // CSR: src sorted by dst
__device__ float g_enorm[MAX_E];        // CSR: edge norm sorted by dst
__device__ __align__(16) float g_bufA[MAX_N * 96];
__device__ __align__(16) float g_bufB[MAX_N * 96];
__device__ __align__(16) float g_bufH[MAX_N * 96];

// ---------------- setup: degree ------------------------------------------------
__global__ void k_zero_deg(int n) {
    int i = blockIdx.x * blockDim.x + threadIdx.x;
    if (i < n) g_deg[i] = 0;
}

// edge_index is INT32 (JAX x64 disabled).
__global__ void k_count(const int* __restrict__ ei, int e, int n) {
    int i = blockIdx.x * blockDim.x + threadIdx.x;
    if (i >= e) return;
    int s = ei[i];
    int d = ei[e + i];
    if ((unsigned)s >= (unsigned)n) s = 0;   // surface as rel_err, never trap
    if ((unsigned)d >= (unsigned)n) d = 0;
    g_src[i] = s;
    g_dst[i] = d;
    atomicAdd(&g_deg[d], 1);
}

__global__ void k_rsqrt(int n) {
    int i = blockIdx.x * blockDim.x + threadIdx.x;
    if (i < n) g_dis[i] = rsqrtf((float)g_deg[i] + 1.0f);
}

// ---------------- 3-kernel exclusive scan of g_deg -> g_row --------------------
__global__ void k_scan1(int n) {
    __shared__ int sd[SCAN_B];
    int t = threadIdx.x;
    int gi = blockIdx.x * SCAN_B + t;
    int v = (gi < n) ? g_deg[gi] : 0;
    sd[t] = v;
    __syncthreads();
    for (int off = 1; off < SCAN_B; off <<= 1) {
        int x = (t >= off) ? sd[t - off] : 0;
        __syncthreads();
        sd[t] += x;
        __syncthreads();
    }
    if (gi < n) g_row[gi] = sd[t] - v;          // exclusive
    if (t == SCAN_B - 1) g_bsum[blockIdx.x] = sd[t];
}

__global__ void k_scan2(int nb) {
    __shared__ int sd[SCAN_B];
    int t = threadIdx.x;
    int v = (t < nb) ? g_bsum[t] : 0;
    sd[t] = v;
    __syncthreads();
    for (int off = 1; off < SCAN_B; off <<= 1) {
        int x = (t >= off) ? sd[t - off] : 0;
        __syncthreads();
        sd[t] += x;
        __syncthreads();
    }
    if (t < nb) g_boff[t] = sd[t] - v;          // exclusive
}

__global__ void k_scan3(int n) {
    int i = blockIdx.x * blockDim.x + threadIdx.x;
    if (i >= n) return;
    int r = g_row[i] + g_boff[i / SCAN_B];
    g_row[i] = r;
    g_cur[i] = r;
}

// ---------------- bucket edges by dst (fuses norm compute) --------------------
__global__ void k_bucket(int e) {
    int i = blockIdx.x * blockDim.x + threadIdx.x;
    if (i >= e) return;
    int s = g_src[i];
    int d = g_dst[i];
    int pos = atomicAdd(&g_cur[d], 1);
    g_esrc[pos] = s;
    g_enorm[pos] = g_dis[s] * g_dis[d];
}

// ---------------- gather aggregation: out[v] = sum + h[v]*d2 (+bias) ----------
// G = F/4 threads per node; edge meta broadcast across the group; 2x unrolled.
template <int F, bool BIAS>
__global__ void __launch_bounds__(256)
k_agg(const float* __restrict__ h, const float* __restrict__ bias,
      float* __restrict__ out, int n) {
    constexpr int G = F / 4;
    int tid = blockIdx.x * blockDim.x + threadIdx.x;
    int node = tid / G;
    int v = tid - node * G;
    if (node >= n) return;

    float dis = g_dis[node];
    float d2 = dis * dis;
    float4 acc = *reinterpret_cast<const float4*>(h + (size_t)node * F + (v << 2));
    acc.x *= d2; acc.y *= d2; acc.z *= d2; acc.w *= d2;
    if (BIAS) {
        float4 bv = *reinterpret_cast<const float4*>(bias + (v << 2));
        acc.x += bv.x; acc.y += bv.y; acc.z += bv.z; acc.w += bv.w;
    }

    int start = g_row[node];
    int deg = g_deg[node];
    int j = 0;
    for (; j + 2 <= deg; j += 2) {
        int s0 = g_esrc[start + j];
        int s1 = g_esrc[start + j + 1];
        float w0 = g_enorm[start + j];
        float w1 = g_enorm[start + j + 1];
        float4 a = *reinterpret_cast<const float4*>(h + (size_t)s0 * F + (v << 2));
        float4 b = *reinterpret_cast<const float4*>(h + (size_t)s1 * F + (v << 2));
        acc.x += a.x * w0; acc.y += a.y * w0; acc.z += a.z * w0; acc.w += a.w * w0;
        acc.x += b.x * w1; acc.y += b.y * w1; acc.z += b.z * w1; acc.w += b.w * w1;
    }
    if (j < deg) {
        int s0 = g_esrc[start + j];
        float w0 = g_enorm[start + j];
        float4 a = *reinterpret_cast<const float4*>(h + (size_t)s0 * F + (v << 2));
        acc.x += a.x * w0; acc.y += a.y * w0; acc.z += a.z * w0; acc.w += a.w * w0;
    }
    *reinterpret_cast<float4*>(out + (size_t)node * F + (v << 2)) = acc;
}

// ---------------- GEMM: out = act(in) @ W (+bh) --------------------------------
template <int FIN, int FOUT, bool RELU, bool BIASH>
__global__ void __launch_bounds__(128)
k_gemm(const float* __restrict__ in, const float* __restrict__ W,
       const float* __restrict__ bh, float* __restrict__ out, int n) {
    extern __shared__ float sm[];
    float* Xs = sm;                 // [FIN][129]
    float* Ws = sm + FIN * 129;     // [FIN][FOUT]
    const int tid = threadIdx.x;
    const int base = blockIdx.x * 128;

    for (int i = tid; i < FIN * FOUT; i += 128) Ws[i] = W[i];

    const int rows = (n - base < 128) ? (n - base) : 128;
    for (int i = tid; i < FIN * 128; i += 128) {
        int nl = i / FIN;
        int k = i - nl * FIN;
        float v = 0.0f;
        if (nl < rows) {
            v = in[(size_t)(base + nl) * FIN + k];
            if (RELU) v = fmaxf(v, 0.0f);
        }
        Xs[k * 129 + nl] = v;
    }
    __syncthreads();

    const int node = base + tid;
    const bool valid = node < n;

    for (int c0 = 0; c0 < FOUT; c0 += 16) {
        float acc[16];
#pragma unroll
        for (int j = 0; j < 16; j++) acc[j] = BIASH ? __ldg(&bh[c0 + j]) : 0.0f;

#pragma unroll 4
        for (int k = 0; k < FIN; k++) {
            float xv = Xs[k * 129 + tid];
            const float4* wr = reinterpret_cast<const float4*>(Ws + k * FOUT + c0);
#pragma unroll
            for (int j = 0; j < 4; j++) {
                float4 w = wr[j];
                acc[4 * j + 0] += xv * w.x;
                acc[4 * j + 1] += xv * w.y;
                acc[4 * j + 2] += xv * w.z;
                acc[4 * j + 3] += xv * w.w;
            }
        }

        if (valid) {
            float4* op = reinterpret_cast<float4*>(out + (size_t)node * FOUT + c0);
#pragma unroll
            for (int j = 0; j < 4; j++) {
                float4 o = {acc[4 * j], acc[4 * j + 1], acc[4 * j + 2], acc[4 * j + 3]};
                op[j] = o;
            }
        }
    }
}

// ---------------- launch -------------------------------------------------------
extern "C" void kernel_launch(void* const* d_in, const int* in_sizes, int n_in,
                              void* d_out, int out_size) {
    const float* x  = (const float*)d_in[0];
    const int*   ei = (const int*)d_in[1];   // int32
    const float* W1 = (const float*)d_in[2]; const float* b1 = (const float*)d_in[3];
    const float* W2 = (const float*)d_in[4]; const float* b2 = (const float*)d_in[5];
    const float* W3 = (const float*)d_in[6]; const float* b3 = (const float*)d_in[7];
    const float* W4 = (const float*)d_in[8]; const float* b4 = (const float*)d_in[9];
    float* out = (float*)d_out;

    const int n = in_sizes[0] / 64;
    const int e = in_sizes[1] / 2;

    float *bufA, *bufB, *bufH;
    cudaGetSymbolAddress((void**)&bufA, g_bufA);
    cudaGetSymbolAddress((void**)&bufB, g_bufB);
    cudaGetSymbolAddress((void**)&bufH, g_bufH);

    const int s1 = (64 * 129 + 64 * 96) * 4;
    const int s2 = (96 * 129 + 96 * 64) * 4;
    const int s3 = (64 * 129 + 64 * 32) * 4;
    const int s4 = (32 * 129 + 32 * 16) * 4;
    cudaFuncSetAttribute(k_gemm<64, 96, false, true>, cudaFuncAttributeMaxDynamicSharedMemorySize, s1);
    cudaFuncSetAttribute(k_gemm<96, 64, true, false>, cudaFuncAttributeMaxDynamicSharedMemorySize, s2);
    cudaFuncSetAttribute(k_gemm<64, 32, true, false>, cudaFuncAttributeMaxDynamicSharedMemorySize, s3);
    cudaFuncSetAttribute(k_gemm<32, 16, true, false>, cudaFuncAttributeMaxDynamicSharedMemorySize, s4);

    const int TB = 256;
    const int nb_n = (n + TB - 1) / TB;
    const int nb_e = (e + TB - 1) / TB;
    const int gblk = (n + 127) / 128;
    const int nscan = (n + SCAN_B - 1) / SCAN_B;   // 196 for n=100000

    // ---- CSR build (per replay; deterministic work) ----
    k_zero_deg<<<nb_n, TB>>>(n);
    k_count<<<nb_e, TB>>>(ei, e, n);
    k_rsqrt<<<nb_n, TB>>>(n);
    k_scan1<<<nscan, SCAN_B>>>(n);
    k_scan2<<<1, SCAN_B>>>(nscan);
    k_scan3<<<nb_n, TB>>>(n);
    k_bucket<<<nb_e, TB>>>(e);

    // ---- layer 1: agg1 = Ax (width 64), then GEMM 64->96 (+b1) ----
    k_agg<64, false><<<(n * 16 + TB - 1) / TB, TB>>>(x, nullptr, bufA, n);
    k_gemm<64, 96, false, true><<<gblk, 128, s1>>>(bufA, W1, b1, bufB, n);

    // ---- layer 2: t = relu(h1)@W2 ; agg2 = A t + b2 ----
    k_gemm<96, 64, true, false><<<gblk, 128, s2>>>(bufB, W2, nullptr, bufH, n);
    k_agg<64, true><<<(n * 16 + TB - 1) / TB, TB>>>(bufH, b2, bufA, n);

    // ---- layer 3: t = relu(agg2)@W3 ; agg3 = A t + b3 ----
    k_gemm<64, 32, true, false><<<gblk, 128, s3>>>(bufA, W3, nullptr, bufH, n);
    k_agg<32, true><<<(n * 8 + TB - 1) / TB, TB>>>(bufH, b3, bufB, n);

    // ---- layer 4: t = relu(agg3)@W4 ; out = A t + b4 ----
    k_gemm<32, 16, true, false><<<gblk, 128, s4>>>(bufB, W4, nullptr, bufH, n);
    k_agg<16, true><<<(n * 4 + TB - 1) / TB, TB>>>(bufH, b4, out, n);
}

// round 7
// speedup vs baseline: 2.2413x; 1.0026x over previous
#include <cuda_runtime.h>

typedef unsigned long long ull;

// ---------------- problem constants ------------------------------------------
#define MAX_N 100000
#define MAX_E 1600000
#define SCAN_B 512

// ---------------- device scratch (allocation-free rule) ----------------------
__device__ int   g_deg[MAX_N];          // in-degree (dst), excl. self loop
__device__ float g_dis[MAX_N];          // (deg+1)^{-1/2}
__device__ int   g_row[MAX_N];          // CSR row start
__device__ int   g_cur[MAX_N];          // bucket cursor
__device__ int   g_bsum[SCAN_B];        // scan partials
__device__ int   g_boff[SCAN_B];
__device__ int2  g_epack[MAX_E];        // CSR: {src, norm_bits} sorted by dst
__device__ __align__(16) float g_bufA[MAX_N * 96];
__device__ __align__(16) float g_bufB[MAX_N * 96];
__device__ __align__(16) float g_bufH[MAX_N * 96];

// ---------------- packed f32x2 helpers ----------------------------------------
__device__ __forceinline__ ull pack2(float x) {
    ull r;
    asm("mov.b64 %0, {%1, %1};" : "=l"(r) : "r"(__float_as_uint(x)));
    return r;
}
__device__ __forceinline__ ull fma2(ull a, ull b, ull c) {
    ull d;
    asm("fma.rn.f32x2 %0, %1, %2, %3;" : "=l"(d) : "l"(a), "l"(b), "l"(c));
    return d;
}

// ---------------- setup: degree ------------------------------------------------
__global__ void k_zero_deg(int n) {
    int i = blockIdx.x * blockDim.x + threadIdx.x;
    if (i < n) g_deg[i] = 0;
}

// edge_index is INT32 (JAX x64 disabled).
__global__ void k_count(const int* __restrict__ ei, int e, int n) {
    int i = blockIdx.x * blockDim.x + threadIdx.x;
    if (i >= e) return;
    int d = ei[e + i];
    if ((unsigned)d >= (unsigned)n) d = 0;   // surface as rel_err, never trap
    atomicAdd(&g_deg[d], 1);
}

// ---------------- exclusive scan of g_deg -> g_row (+ fused rsqrt) -------------
__global__ void k_scan1(int n) {
    __shared__ int sd[SCAN_B];
    int t = threadIdx.x;
    int gi = blockIdx.x * SCAN_B + t;
    int v = (gi < n) ? g_deg[gi] : 0;
    if (gi < n) g_dis[gi] = rsqrtf((float)v + 1.0f);
    sd[t] = v;
    __syncthreads();
    for (int off = 1; off < SCAN_B; off <<= 1) {
        int x = (t >= off) ? sd[t - off] : 0;
        __syncthreads();
        sd[t] += x;
        __syncthreads();
    }
    if (gi < n) g_row[gi] = sd[t] - v;          // exclusive
    if (t == SCAN_B - 1) g_bsum[blockIdx.x] = sd[t];
}

__global__ void k_scan2(int nb) {
    __shared__ int sd[SCAN_B];
    int t = threadIdx.x;
    int v = (t < nb) ? g_bsum[t] : 0;
    sd[t] = v;
    __syncthreads();
    for (int off = 1; off < SCAN_B; off <<= 1) {
        int x = (t >= off) ? sd[t - off] : 0;
        __syncthreads();
        sd[t] += x;
        __syncthreads();
    }
    if (t < nb) g_boff[t] = sd[t] - v;          // exclusive
}

__global__ void k_scan3(int n) {
    int i = blockIdx.x * blockDim.x + threadIdx.x;
    if (i >= n) return;
    int r = g_row[i] + g_boff[i / SCAN_B];
    g_row[i] = r;
    g_cur[i] = r;
}

// ---------------- bucket edges by dst (fuses norm compute, packed meta) --------
__global__ void k_bucket(const int* __restrict__ ei, int e, int n) {
    int i = blockIdx.x * blockDim.x + threadIdx.x;
    if (i >= e) return;
    int s = ei[i];
    int d = ei[e + i];
    if ((unsigned)s >= (unsigned)n) s = 0;
    if ((unsigned)d >= (unsigned)n) d = 0;
    int pos = atomicAdd(&g_cur[d], 1);
    g_epack[pos] = make_int2(s, __float_as_int(g_dis[s] * g_dis[d]));
}

// ---------------- gather aggregation: out[v] = sum + h[v]*d2 (+bias) ----------
// G = F/4 threads per node; packed edge meta, 4x unrolled for MLP.
template <int F, bool BIAS>
__global__ void __launch_bounds__(256)
k_agg(const float* __restrict__ h, const float* __restrict__ bias,
      float* __restrict__ out, int n) {
    constexpr int G = F / 4;
    int tid = blockIdx.x * blockDim.x + threadIdx.x;
    int node = tid / G;
    int v = tid - node * G;
    if (node >= n) return;

    float dis = g_dis[node];
    float d2 = dis * dis;
    float4 acc = *reinterpret_cast<const float4*>(h + (size_t)node * F + (v << 2));
    acc.x *= d2; acc.y *= d2; acc.z *= d2; acc.w *= d2;
    if (BIAS) {
        float4 bv = *reinterpret_cast<const float4*>(bias + (v << 2));
        acc.x += bv.x; acc.y += bv.y; acc.z += bv.z; acc.w += bv.w;
    }

    int j = g_row[node];
    int end = j + g_deg[node];
    for (; j + 4 <= end; j += 4) {
        int2 p0 = g_epack[j + 0];
        int2 p1 = g_epack[j + 1];
        int2 p2 = g_epack[j + 2];
        int2 p3 = g_epack[j + 3];
        float4 a0 = *reinterpret_cast<const float4*>(h + (size_t)p0.x * F + (v << 2));
        float4 a1 = *reinterpret_cast<const float4*>(h + (size_t)p1.x * F + (v << 2));
        float4 a2 = *reinterpret_cast<const float4*>(h + (size_t)p2.x * F + (v << 2));
        float4 a3 = *reinterpret_cast<const float4*>(h + (size_t)p3.x * F + (v << 2));
        float w0 = __int_as_float(p0.y), w1 = __int_as_float(p1.y);
        float w2 = __int_as_float(p2.y), w3 = __int_as_float(p3.y);
        acc.x += a0.x * w0; acc.y += a0.y * w0; acc.z += a0.z * w0; acc.w += a0.w * w0;
        acc.x += a1.x * w1; acc.y += a1.y * w1; acc.z += a1.z * w1; acc.w += a1.w * w1;
        acc.x += a2.x * w2; acc.y += a2.y * w2; acc.z += a2.z * w2; acc.w += a2.w * w2;
        acc.x += a3.x * w3; acc.y += a3.y * w3; acc.z += a3.z * w3; acc.w += a3.w * w3;
    }
    for (; j < end; j++) {
        int2 p = g_epack[j];
        float w = __int_as_float(p.y);
        float4 a = *reinterpret_cast<const float4*>(h + (size_t)p.x * F + (v << 2));
        acc.x += a.x * w; acc.y += a.y * w; acc.z += a.z * w; acc.w += a.w * w;
    }
    *reinterpret_cast<float4*>(out + (size_t)node * F + (v << 2)) = acc;
}

// ---------------- GEMM: out = act(in) @ W (+bh), packed f32x2 FMA --------------
template <int FIN, int FOUT, bool RELU, bool BIASH>
__global__ void __launch_bounds__(128)
k_gemm(const float* __restrict__ in, const float* __restrict__ W,
       const float* __restrict__ bh, float* __restrict__ out, int n) {
    extern __shared__ float sm[];
    float* Xs = sm;                 // [FIN][129]
    float* Ws = sm + FIN * 129;     // [FIN][FOUT]
    const int tid = threadIdx.x;
    const int base = blockIdx.x * 128;

    for (int i = tid; i < FIN * FOUT; i += 128) Ws[i] = W[i];

    const int rows = (n - base < 128) ? (n - base) : 128;
    for (int i = tid; i < FIN * 128; i += 128) {
        int nl = i / FIN;
        int k = i - nl * FIN;
        float v = 0.0f;
        if (nl < rows) {
            v = in[(size_t)(base + nl) * FIN + k];
            if (RELU) v = fmaxf(v, 0.0f);
        }
        Xs[k * 129 + nl] = v;
    }
    __syncthreads();

    const int node = base + tid;
    const bool valid = node < n;

    constexpr int CH = (FOUT % 32 == 0) ? 32 : FOUT;   // 32 or 16
    constexpr int NP = CH / 2;                          // packed accumulators

    for (int c0 = 0; c0 < FOUT; c0 += CH) {
        ull acc[NP];
#pragma unroll
        for (int j = 0; j < NP; j++)
            acc[j] = BIASH ? *reinterpret_cast<const ull*>(bh + c0 + 2 * j) : 0ull;

#pragma unroll 4
        for (int k = 0; k < FIN; k++) {
            ull xx = pack2(Xs[k * 129 + tid]);
            const ull* wr = reinterpret_cast<const ull*>(Ws + k * FOUT + c0);
#pragma unroll
            for (int j = 0; j < NP; j++)
                acc[j] = fma2(xx, wr[j], acc[j]);
        }

        if (valid) {
            ull* op = reinterpret_cast<ull*>(out + (size_t)node * FOUT + c0);
#pragma unroll
            for (int j = 0; j < NP; j++) op[j] = acc[j];
        }
    }
}

// ---------------- launch -------------------------------------------------------
extern "C" void kernel_launch(void* const* d_in, const int* in_sizes, int n_in,
                              void* d_out, int out_size) {
    const float* x  = (const float*)d_in[0];
    const int*   ei = (const int*)d_in[1];   // int32
    const float* W1 = (const float*)d_in[2]; const float* b1 = (const float*)d_in[3];
    const float* W2 = (const float*)d_in[4]; const float* b2 = (const float*)d_in[5];
    const float* W3 = (const float*)d_in[6]; const float* b3 = (const float*)d_in[7];
    const float* W4 = (const float*)d_in[8]; const float* b4 = (const float*)d_in[9];
    float* out = (float*)d_out;

    const int n = in_sizes[0] / 64;
    const int e = in_sizes[1] / 2;

    float *bufA, *bufB, *bufH;
    cudaGetSymbolAddress((void**)&bufA, g_bufA);
    cudaGetSymbolAddress((void**)&bufB, g_bufB);
    cudaGetSymbolAddress((void**)&bufH, g_bufH);

    const int s1 = (64 * 129 + 64 * 96) * 4;
    const int s2 = (96 * 129 + 96 * 64) * 4;
    const int s3 = (64 * 129 + 64 * 32) * 4;
    const int s4 = (32 * 129 + 32 * 16) * 4;
    cudaFuncSetAttribute(k_gemm<64, 96, false, true>, cudaFuncAttributeMaxDynamicSharedMemorySize, s1);
    cudaFuncSetAttribute(k_gemm<96, 64, true, false>, cudaFuncAttributeMaxDynamicSharedMemorySize, s2);
    cudaFuncSetAttribute(k_gemm<64, 32, true, false>, cudaFuncAttributeMaxDynamicSharedMemorySize, s3);
    cudaFuncSetAttribute(k_gemm<32, 16, true, false>, cudaFuncAttributeMaxDynamicSharedMemorySize, s4);

    const int TB = 256;
    const int nb_n = (n + TB - 1) / TB;
    const int nb_e = (e + TB - 1) / TB;
    const int gblk = (n + 127) / 128;
    const int nscan = (n + SCAN_B - 1) / SCAN_B;   // 196 for n=100000

    // ---- CSR build (per replay; deterministic work) ----
    k_zero_deg<<<nb_n, TB>>>(n);
    k_count<<<nb_e, TB>>>(ei, e, n);
    k_scan1<<<nscan, SCAN_B>>>(n);       // also computes g_dis
    k_scan2<<<1, SCAN_B>>>(nscan);
    k_scan3<<<nb_n, TB>>>(n);
    k_bucket<<<nb_e, TB>>>(ei, e, n);

    // ---- layer 1: agg1 = Ax (width 64), then GEMM 64->96 (+b1) ----
    k_agg<64, false><<<(n * 16 + TB - 1) / TB, TB>>>(x, nullptr, bufA, n);
    k_gemm<64, 96, false, true><<<gblk, 128, s1>>>(bufA, W1, b1, bufB, n);

    // ---- layer 2: t = relu(h1)@W2 ; agg2 = A t + b2 ----
    k_gemm<96, 64, true, false><<<gblk, 128, s2>>>(bufB, W2, nullptr, bufH, n);
    k_agg<64, true><<<(n * 16 + TB - 1) / TB, TB>>>(bufH, b2, bufA, n);

    // ---- layer 3: t = relu(agg2)@W3 ; agg3 = A t + b3 ----
    k_gemm<64, 32, true, false><<<gblk, 128, s3>>>(bufA, W3, nullptr, bufH, n);
    k_agg<32, true><<<(n * 8 + TB - 1) / TB, TB>>>(bufH, b3, bufB, n);

    // ---- layer 4: t = relu(agg3)@W4 ; out = A t + b4 ----
    k_gemm<32, 16, true, false><<<gblk, 128, s4>>>(bufB, W4, nullptr, bufH, n);
    k_agg<16, true><<<(n * 4 + TB - 1) / TB, TB>>>(bufH, b4, out, n);
}